// round 11
// baseline (speedup 1.0000x reference)
#include <cuda_runtime.h>

// dim = 4096 = 2^12, J = dim-1 = 4095 RZ angles, input_dim = 4096.
// Only inputs[0, :] is used by the reference.
#define NQ      12
#define DIMP    4096
#define JCOLS   4095
#define KSPLIT  32
#define KCHUNK  128          // 4096 / KSPLIT
#define CBLK    256          // columns (threads) per gemv block

#define N_INPUTS_ELEMS (1024 * 4096)     // 4194304
#define N_WEIGHT_ELEMS (4096 * 4095)     // 16773120

#define MAX_GATES 8192                   // actual count: 8178

__device__ float          g_part[KSPLIT][DIMP];
__device__ unsigned short g_mask[DIMP];
__device__ int            g_gates[MAX_GATES];

// -------------------------------------------------------------------------
// Kernel 0: LINE-BY-LINE port of the reference mask construction
// (executed in R9; produces masks identical to the closed form).
// Explicit-stack emulation of rec() + verbatim sequential backward walk.
// -------------------------------------------------------------------------
__global__ void mask_literal_kernel()
{
    if (threadIdx.x != 0 || blockIdx.x != 0) return;

    int gn = 0;
    for (int i = 1; i <= NQ; i++) {      // for i in 1..n: rec(i, i-1)
        int num[16], tgt[16], stg[16];
        int sp = 0;
        num[0] = i; tgt[0] = i - 1; stg[0] = 0; sp = 1;
        while (sp > 0) {
            const int f = sp - 1;
            if (num[f] == 1) {
                g_gates[gn++] = (0 << 16) | 0;                 // rz(0)
                sp--;
            } else if (num[f] == 2) {
                const int t = tgt[f];
                g_gates[gn++] = (0 << 16) | t;                 // rz(t)
                g_gates[gn++] = (1 << 16) | (0 << 8) | t;      // cx(0, t)
                g_gates[gn++] = (0 << 16) | t;                 // rz(t)
                sp--;
            } else if (stg[f] == 0) {
                stg[f] = 1;
                num[sp] = num[f] - 1; tgt[sp] = tgt[f]; stg[sp] = 0; sp++;
            } else if (stg[f] == 1) {
                g_gates[gn++] = (1 << 16) | ((num[f] - 2) << 8) | tgt[f];
                stg[f] = 2;
                num[sp] = num[f] - 1; tgt[sp] = tgt[f]; stg[sp] = 0; sp++;
            } else {
                sp--;
            }
        }
    }

    int masks[NQ];
    for (int q = 0; q < NQ; q++) masks[q] = 1 << (NQ - 1 - q);
    int j = JCOLS;
    for (int g = gn - 1; g >= 0; g--) {
        const int e = g_gates[g];
        if ((e >> 16) == 0) { j--; g_mask[j] = (unsigned short)masks[e & 0xFF]; }
        else                { masks[e & 0xFF] ^= masks[(e >> 8) & 0xFF]; }
    }
    g_mask[JCOLS] = 0;
}

// -------------------------------------------------------------------------
// Kernel 1: theta_raw[j] = sum_k W[k*4095 + j] * x[k]  (numpy C-order).
// Split-K over 32 chunks; consecutive threads -> consecutive j (coalesced).
// -------------------------------------------------------------------------
__global__ void __launch_bounds__(CBLK) gemv_kernel(
    const float* __restrict__ W, const float* __restrict__ x)
{
    __shared__ float xs[KCHUNK];
    const int j  = blockIdx.x * CBLK + threadIdx.x;
    const int k0 = blockIdx.y * KCHUNK;

    if (threadIdx.x < KCHUNK) xs[threadIdx.x] = x[k0 + threadIdx.x];
    __syncthreads();

    if (j < JCOLS) {
        const float* wp = W + (size_t)k0 * JCOLS + j;
        float acc = 0.f;
        #pragma unroll 16
        for (int kk = 0; kk < KCHUNK; kk++) {
            acc += wp[(size_t)kk * JCOLS] * xs[kk];
        }
        g_part[blockIdx.y][j] = acc;
    }
}

// -------------------------------------------------------------------------
// Kernel 2: proven phase pipeline, PLANAR float32 output layout:
//   out_f[x]        = cos(phase[x]) / 64     (all real parts first)
//   out_f[4096 + x] = sin(phase[x]) / 64     (then all imag parts)
// phase[x] = sum_j (2*par-1)*0.5*theta_j, theta_j = sqrt(0.5)*theta_raw_j.
// -------------------------------------------------------------------------
__global__ void __launch_bounds__(1024) phase_kernel(float* __restrict__ outf)
{
    __shared__ float          th [DIMP];
    __shared__ unsigned short msk[DIMP];
    const int t = threadIdx.x;

    #pragma unroll
    for (int jb = 0; jb < 4; jb++) {
        const int j = t + jb * 1024;
        float tv = 0.f;
        if (j < JCOLS) {
            float s = 0.f;
            #pragma unroll
            for (int r = 0; r < KSPLIT; r++) s += g_part[r][j];
            tv = s * (-0.35355339059327376f);   // -0.5 * sqrt(0.5)
        }
        th [j] = tv;
        msk[j] = g_mask[j];
    }
    __syncthreads();

    const int lane = t & 31;
    const int x    = blockIdx.x * 32 + (t >> 5);

    float acc = 0.f;
    #pragma unroll 4
    for (int it = 0; it < DIMP / 32; it++) {
        const int j = it * 32 + lane;
        const float    tv = th[j];
        const unsigned m  = msk[j];
        acc += (__popc((unsigned)x & m) & 1) ? -tv : tv;
    }
    #pragma unroll
    for (int off = 16; off; off >>= 1)
        acc += __shfl_down_sync(0xFFFFFFFFu, acc, off);

    if (lane == 0) {
        float sn, cs;
        sincosf(acc, &sn, &cs);
        outf[x]        = cs * (1.0f / 64.0f);   // real plane
        outf[DIMP + x] = sn * (1.0f / 64.0f);   // imag plane
    }
}

// Diagnostic: zero output -> rel_err exactly 1.000 signals size anomaly.
__global__ void zero_kernel(float* __restrict__ outf, int n)
{
    const int i = blockIdx.x * blockDim.x + threadIdx.x;
    if (i < n) outf[i] = 0.f;
}

// -------------------------------------------------------------------------
extern "C" void kernel_launch(void* const* d_in, const int* in_sizes, int n_in,
                              void* d_out, int out_size)
{
    const float* inputs = nullptr;
    const float* W      = nullptr;
    for (int i = 0; i < n_in; i++) {
        if (in_sizes[i] == N_WEIGHT_ELEMS)      W      = (const float*)d_in[i];
        else if (in_sizes[i] == N_INPUTS_ELEMS) inputs = (const float*)d_in[i];
    }

    if (!inputs || !W) {
        // Sizes differ from the assumed {4194304, 16773120}: flag via
        // zero output (rel_err reads exactly 1.000).
        const int nf = DIMP * 2;
        zero_kernel<<<(nf + 255) / 256, 256>>>((float*)d_out, nf);
        return;
    }

    mask_literal_kernel<<<1, 32>>>();
    dim3 grid(DIMP / CBLK, KSPLIT);
    gemv_kernel<<<grid, CBLK>>>(W, inputs);
    phase_kernel<<<128, 1024>>>((float*)d_out);
}

// round 13
// speedup vs baseline: 65.7707x; 65.7707x over previous
#include <cuda_runtime.h>

// dim = 4096 = 2^12, J = dim-1 = 4095 RZ angles, input_dim = 4096.
// Only inputs[0, :] is used by the reference.
#define NQ      12
#define DIMP    4096
#define JCOLS   4095
#define KSPLIT  32
#define KCHUNK  128          // 4096 / KSPLIT
#define CBLK    256          // columns (threads) per gemv block

#define N_INPUTS_ELEMS (1024 * 4096)     // 4194304
#define N_WEIGHT_ELEMS (4096 * 4095)     // 16773120

__device__ float g_part[KSPLIT][DIMP];

// -------------------------------------------------------------------------
// Kernel 1: theta_raw[j] = sum_k W[k*4095 + j] * x[k]  (numpy C-order).
// Split-K over 32 chunks; consecutive threads -> consecutive j (coalesced).
// Streams 67 MB of W; L2-resident on graph replays.
// -------------------------------------------------------------------------
__global__ void __launch_bounds__(CBLK) gemv_kernel(
    const float* __restrict__ W, const float* __restrict__ x)
{
    __shared__ float xs[KCHUNK];
    const int j  = blockIdx.x * CBLK + threadIdx.x;
    const int k0 = blockIdx.y * KCHUNK;

    if (threadIdx.x < KCHUNK) xs[threadIdx.x] = x[k0 + threadIdx.x];
    __syncthreads();

    if (j < JCOLS) {
        const float* wp = W + (size_t)k0 * JCOLS + j;
        float acc = 0.f;
        #pragma unroll 16
        for (int kk = 0; kk < KCHUNK; kk++) {
            acc += wp[(size_t)kk * JCOLS] * xs[kk];
        }
        g_part[blockIdx.y][j] = acc;
    }
}

// -------------------------------------------------------------------------
// Kernel 2: phase pipeline with INLINE CLOSED-FORM masks.
// The closed form is bit-identical to the reference's literal gate
// backprop: R4 (closed form) and R9 (assumption-free literal port)
// produced byte-identical outputs; R11 (literal port) passed.
//   p = j+1; block i = msb(p)+1; k = p - 2^(i-1);
//   u = bitrev_{i-1}(gray(k)) ^ 1  (i>=2), 0 (i==1)
//   mask = (1 << (NQ-i)) | (u << (NQ-i+1))
// phase[x] = sum_j (2*par-1)*0.5*theta_j, theta_j = sqrt(0.5)*theta_raw_j.
// PLANAR float32 output (the proven layout):
//   out[x] = cos(phase)/64 ; out[4096+x] = sin(phase)/64.
// -------------------------------------------------------------------------
__global__ void __launch_bounds__(1024) phase_kernel(float* __restrict__ outf)
{
    __shared__ float          th [DIMP];
    __shared__ unsigned short msk[DIMP];
    const int t = threadIdx.x;

    #pragma unroll
    for (int jb = 0; jb < 4; jb++) {
        const int j = t + jb * 1024;
        float    tv = 0.f;
        unsigned m  = 0;
        if (j < JCOLS) {
            float s = 0.f;
            #pragma unroll
            for (int r = 0; r < KSPLIT; r++) s += g_part[r][j];
            tv = s * (-0.35355339059327376f);   // -0.5 * sqrt(0.5)

            const int p = j + 1;
            const int i = 32 - __clz((unsigned)p);   // block 1..12
            const int k = p - (1 << (i - 1));
            const int width = i - 1;
            unsigned u = 0;
            if (width > 0) {
                const unsigned g = (unsigned)k ^ ((unsigned)k >> 1);
                u = (__brev(g) >> (32 - width)) ^ 1u;
            }
            m = (1u << (NQ - i)) | (u << (NQ - i + 1));
        }
        th [j] = tv;
        msk[j] = (unsigned short)m;              // j==4095 -> 0 mask, 0 theta
    }
    __syncthreads();

    const int lane = t & 31;
    const int x    = blockIdx.x * 32 + (t >> 5); // one warp per output x

    float acc = 0.f;
    #pragma unroll 4
    for (int it = 0; it < DIMP / 32; it++) {
        const int j = it * 32 + lane;
        const float    tv = th[j];
        const unsigned m  = msk[j];
        // par odd -> S=+1 -> -tv(=+0.5*theta); par even -> S=-1 -> +tv
        acc += (__popc((unsigned)x & m) & 1) ? -tv : tv;
    }
    #pragma unroll
    for (int off = 16; off; off >>= 1)
        acc += __shfl_down_sync(0xFFFFFFFFu, acc, off);

    if (lane == 0) {
        float sn, cs;
        sincosf(acc, &sn, &cs);
        outf[x]        = cs * (1.0f / 64.0f);    // real plane
        outf[DIMP + x] = sn * (1.0f / 64.0f);    // imag plane
    }
}

// Diagnostic: zero output -> rel_err exactly 1.000 signals size anomaly.
__global__ void zero_kernel(float* __restrict__ outf, int n)
{
    const int i = blockIdx.x * blockDim.x + threadIdx.x;
    if (i < n) outf[i] = 0.f;
}

// -------------------------------------------------------------------------
extern "C" void kernel_launch(void* const* d_in, const int* in_sizes, int n_in,
                              void* d_out, int out_size)
{
    const float* inputs = nullptr;
    const float* W      = nullptr;
    for (int i = 0; i < n_in; i++) {
        if (in_sizes[i] == N_WEIGHT_ELEMS)      W      = (const float*)d_in[i];
        else if (in_sizes[i] == N_INPUTS_ELEMS) inputs = (const float*)d_in[i];
    }

    if (!inputs || !W) {
        const int nf = DIMP * 2;
        zero_kernel<<<(nf + 255) / 256, 256>>>((float*)d_out, nf);
        return;
    }

    dim3 grid(DIMP / CBLK, KSPLIT);              // 16 x 32 blocks
    gemv_kernel<<<grid, CBLK>>>(W, inputs);
    phase_kernel<<<128, 1024>>>((float*)d_out);
}

// round 16
// speedup vs baseline: 71.8211x; 1.0920x over previous
#include <cuda_runtime.h>

// dim = 4096 = 2^12, J = dim-1 = 4095 RZ angles, input_dim = 4096.
// Only inputs[0, :] is used by the reference.
#define NQ      12
#define DIMP    4096
#define JCOLS   4095
#define KSPLIT  32
#define KCHUNK  128          // 4096 / KSPLIT
#define CBLK    256          // columns (threads) per gemv block

#define N_INPUTS_ELEMS (1024 * 4096)     // 4194304
#define N_WEIGHT_ELEMS (4096 * 4095)     // 16773120

__device__ float g_part[KSPLIT][DIMP];

// -------------------------------------------------------------------------
// Kernel 1: theta_raw[j] = sum_k W[k*4095 + j] * x[k]  (numpy C-order).
// Split-K over 32 chunks; consecutive threads -> consecutive j (coalesced).
// 67 MB of W, L2-resident on graph replays; ~4.5us, near LTS cap.
// -------------------------------------------------------------------------
__global__ void __launch_bounds__(CBLK) gemv_kernel(
    const float* __restrict__ W, const float* __restrict__ x)
{
    __shared__ float xs[KCHUNK];
    const int j  = blockIdx.x * CBLK + threadIdx.x;
    const int k0 = blockIdx.y * KCHUNK;

    if (threadIdx.x < KCHUNK) xs[threadIdx.x] = x[k0 + threadIdx.x];
    __syncthreads();

    if (j < JCOLS) {
        const float* wp = W + (size_t)k0 * JCOLS + j;
        float acc = 0.f;
        #pragma unroll 16
        for (int kk = 0; kk < KCHUNK; kk++) {
            acc += wp[(size_t)kk * JCOLS] * xs[kk];
        }
        g_part[blockIdx.y][j] = acc;
    }
}

// -------------------------------------------------------------------------
// Kernel 2: FWHT phase evaluation (replaces the O(D*J) popcount sum;
// proven output-identical to it: R2/R3 vs R4 produced bit-identical
// results with this exact scatter + butterfly).
//   c[mask_j] = -0.5*sqrt(0.5)*theta_raw_j, c[0] = 0
//   phase[x]  = sum_m (-1)^popc(x&m) c[m]   (12-stage smem butterfly)
//   PLANAR float32 out: out[x] = cos/64, out[4096+x] = sin/64.
// Closed-form masks (bit-identical to the reference's gate backprop):
//   p=j+1; i=msb(p)+1; k=p-2^(i-1); u=bitrev_{i-1}(gray(k))^1 (i>=2);
//   mask = (1<<(NQ-i)) | (u<<(NQ-i+1)).
// -------------------------------------------------------------------------
__global__ void __launch_bounds__(1024) fwht_kernel(float* __restrict__ outf)
{
    __shared__ float c[DIMP];
    const int t = threadIdx.x;

    if (t == 0) c[0] = 0.f;   // only index never hit by the scatter

    #pragma unroll
    for (int jb = 0; jb < 4; jb++) {
        const int j = t + jb * 1024;
        if (j < JCOLS) {
            // reduce split-K partials (coalesced along j within each r)
            float s = 0.f;
            #pragma unroll
            for (int r = 0; r < KSPLIT; r++) s += g_part[r][j];

            const int p = j + 1;
            const int i = 32 - __clz((unsigned)p);   // block 1..12
            const int k = p - (1 << (i - 1));
            const int width = i - 1;
            unsigned u = 0;
            if (width > 0) {
                const unsigned g = (unsigned)k ^ ((unsigned)k >> 1);
                u = (__brev(g) >> (32 - width)) ^ 1u;
            }
            const int mask = (1 << (NQ - i)) | ((int)u << (NQ - i + 1));
            c[mask] = s * (-0.35355339059327376f);   // -0.5 * sqrt(0.5)
        }
    }
    __syncthreads();

    // Unnormalized WHT: y[x] = sum_m (-1)^popc(x&m) c[m].
    // Butterflies within a stage are disjoint pairs -> race-free.
    #pragma unroll
    for (int s = 0; s < NQ; s++) {
        const int h = 1 << s;
        #pragma unroll
        for (int bb = 0; bb < 2; bb++) {
            const int b   = t + bb * 1024;           // 2048 butterflies/stage
            const int idx = ((b >> s) << (s + 1)) | (b & (h - 1));
            const float a0 = c[idx];
            const float a1 = c[idx + h];
            c[idx]     = a0 + a1;
            c[idx + h] = a0 - a1;
        }
        __syncthreads();
    }

    // psi = exp(i*phase)/64, planar layout
    const float inv = 1.0f / 64.0f;
    #pragma unroll
    for (int xb = 0; xb < 4; xb++) {
        const int xi = t + xb * 1024;
        float sn, cs;
        sincosf(c[xi], &sn, &cs);
        outf[xi]        = cs * inv;                  // real plane
        outf[DIMP + xi] = sn * inv;                  // imag plane
    }
}

// Diagnostic: zero output -> rel_err exactly 1.000 signals size anomaly.
__global__ void zero_kernel(float* __restrict__ outf, int n)
{
    const int i = blockIdx.x * blockDim.x + threadIdx.x;
    if (i < n) outf[i] = 0.f;
}

// -------------------------------------------------------------------------
extern "C" void kernel_launch(void* const* d_in, const int* in_sizes, int n_in,
                              void* d_out, int out_size)
{
    const float* inputs = nullptr;
    const float* W      = nullptr;
    for (int i = 0; i < n_in; i++) {
        if (in_sizes[i] == N_WEIGHT_ELEMS)      W      = (const float*)d_in[i];
        else if (in_sizes[i] == N_INPUTS_ELEMS) inputs = (const float*)d_in[i];
    }

    if (!inputs || !W) {
        const int nf = DIMP * 2;
        zero_kernel<<<(nf + 255) / 256, 256>>>((float*)d_out, nf);
        return;
    }

    dim3 grid(DIMP / CBLK, KSPLIT);              // 16 x 32 blocks
    gemv_kernel<<<grid, CBLK>>>(W, inputs);
    fwht_kernel<<<1, 1024>>>((float*)d_out);
}